// round 14
// baseline (speedup 1.0000x reference)
#include <cuda_runtime.h>

// Problem geometry: IRREPS_L = [0]*32 + [1]*16 + [2]*8 + [3]*8 + [4]*4
// DIM = 32*1 + 16*3 + 8*5 + 8*7 + 4*9 = 212
#define NBLK 165            // sum of (2l+1)^2 over unique l
#define DIMSZ 212
#define QPB 11236           // float4 quads per batch matrix (212*212/4)
#define NHOT 432            // quads intersecting diagonal blocks
#define NHOT_PAD 512

struct GTab {
    float A[NBLK];
    float Ainv[NBLK];
    unsigned char el[NBLK + 3];
    unsigned char ei[NBLK + 3];
    unsigned char ek[NBLK + 3];
    unsigned char pad_[3];
    int cum[8];                    // {0,1,10,35,84,...}
    short        hdst[NHOT_PAD];   // quad index within 11236
    unsigned int hsrc[NHOT_PAD];   // 4 packed byte-indices into sD (165 => 0)
};

// ===========================================================================
// COMPILE-TIME construction of all tables. Only non-rational primitive is
// sqrt (Newton). Trig eliminated via the Chebyshev recurrence on
// cos(phi)=x/rho, sin(phi)=y/rho. The reference's lstsq solves a CONSISTENT
// system, so its solution (the exact real-SH Wigner matrix of Rx) is
// independent of the sample points; any well-conditioned deterministic set
// reproduces it (validated at rel_err ~8e-8 across rounds 1-11).
// ===========================================================================

constexpr double CPI = 3.14159265358979323846;

constexpr double cfabs(double x) { return x < 0 ? -x : x; }

constexpr double csqrt(double x) {
    if (x <= 0.0) return 0.0;
    double g = x > 1.0 ? x : 1.0;
    for (int i = 0; i < 100; ++i) g = 0.5 * (g + x / g);
    return g;
}

constexpr double dfact(int n) { double r = 1.0; for (int i = 2; i <= n; ++i) r *= (double)i; return r; }

constexpr double urand(unsigned long long& s) {
    s = s * 6364136223846793005ULL + 1442695040888963407ULL;
    return (double)(s >> 11) * (1.0 / 9007199254740992.0);   // [0,1)
}

constexpr void alegendre_c(int l, double x, double* res) {
    for (int m = 0; m <= l; ++m) {
        double pmm = 1.0;
        if (m > 0) {
            double somx2 = csqrt(1.0 - x * x > 0.0 ? 1.0 - x * x : 0.0);
            double fact = 1.0;
            for (int i = 0; i < m; ++i) { pmm = -pmm * fact * somx2; fact += 2.0; }
        }
        if (l == m) { res[m] = pmm; continue; }
        double pmmp1 = x * (2 * m + 1) * pmm;
        if (l == m + 1) { res[m] = pmmp1; continue; }
        double p0 = pmm, p1 = pmmp1, pll = 0.0;
        for (int ll = m + 2; ll <= l; ++ll) {
            pll = ((2 * ll - 1) * x * p1 - (ll + m - 1) * p0) / (ll - m);
            p0 = p1; p1 = pll;
        }
        res[m] = pll;
    }
}

// Real SH without trig: cos(m phi), sin(m phi) via Chebyshev recurrence.
constexpr void rsh_c(int l, double x, double y, double z,
                     const double* Nf, double sq2, double* out) {
    double P[5] = {};
    alegendre_c(l, z, P);
    double rho = csqrt(x * x + y * y);
    double c1 = 1.0, s1 = 0.0;
    if (rho > 1e-300) { c1 = x / rho; s1 = y / rho; }
    double cm[5] = {1.0, 0.0, 0.0, 0.0, 0.0};
    double sm[5] = {0.0, 0.0, 0.0, 0.0, 0.0};
    if (l >= 1) { cm[1] = c1; sm[1] = s1; }
    for (int m = 2; m <= l; ++m) {
        cm[m] = 2.0 * c1 * cm[m - 1] - cm[m - 2];
        sm[m] = 2.0 * c1 * sm[m - 1] - sm[m - 2];
    }
    for (int m = -l; m <= l; ++m) {
        int am = m < 0 ? -m : m;
        double v = 0.0;
        if (m == 0)      v = Nf[0] * P[0];
        else if (m > 0)  v = sq2 * Nf[am] * P[am] * cm[am];
        else             v = sq2 * Nf[am] * P[am] * sm[am];
        out[m + l] = v;
    }
}

// Solve A X = B in place (B <- X), partial pivoting.
constexpr void gsolve_c(int n, int m, double* A, double* B) {
    for (int col = 0; col < n; ++col) {
        int piv = col;
        for (int r2 = col + 1; r2 < n; ++r2)
            if (cfabs(A[r2 * n + col]) > cfabs(A[piv * n + col])) piv = r2;
        if (piv != col) {
            for (int c2 = 0; c2 < n; ++c2) { double t = A[col * n + c2]; A[col * n + c2] = A[piv * n + c2]; A[piv * n + c2] = t; }
            for (int c2 = 0; c2 < m; ++c2) { double t = B[col * m + c2]; B[col * m + c2] = B[piv * m + c2]; B[piv * m + c2] = t; }
        }
        double d = A[col * n + col];
        for (int c2 = col; c2 < n; ++c2) A[col * n + c2] /= d;
        for (int c2 = 0; c2 < m; ++c2) B[col * m + c2] /= d;
        for (int r2 = 0; r2 < n; ++r2) {
            if (r2 == col) continue;
            double f = A[r2 * n + col];
            if (f == 0.0) continue;
            for (int c2 = col; c2 < n; ++c2) A[r2 * n + c2] -= f * A[col * n + c2];
            for (int c2 = 0; c2 < m; ++c2) B[r2 * m + c2] -= f * B[col * m + c2];
        }
    }
}

constexpr GTab make_gtab() {
    GTab g = {};
    const int CNT[5]  = {32, 16, 8, 8, 4};
    const int CUMH[5] = {0, 1, 10, 35, 84};
    const double sq2 = csqrt(2.0);
    const int NP = 80;

    // --- Wigner matrices A (of Rx) and Ainv per l, via normal equations.
    for (int l = 0; l < 5; ++l) {
        int n = 2 * l + 1;
        double Nf[5] = {};
        for (int m = 0; m <= l; ++m)
            Nf[m] = csqrt((2 * l + 1) / (4.0 * CPI) * dfact(l - m) / dfact(l + m));

        double G[81] = {}, C[81] = {};
        unsigned long long seed = 0x9E3779B97F4A7C15ULL + (unsigned long long)l;
        int p = 0;
        int guard = 0;
        while (p < NP && guard < 4 * NP) {
            ++guard;
            double x = 2.0 * urand(seed) - 1.0;
            double y = 2.0 * urand(seed) - 1.0;
            double z = 2.0 * urand(seed) - 1.0;
            double r2 = x * x + y * y + z * z;
            if (r2 < 0.05 || r2 > 1.0) continue;
            double r = csqrt(r2);
            x /= r; y /= r; z /= r;
            double Y[9] = {}, Yr[9] = {};
            rsh_c(l, x, y, z, Nf, sq2, Y);
            rsh_c(l, x, z, -y, Nf, sq2, Yr);   // R = Rx: (x,y,z) -> (x, z, -y)
            for (int a = 0; a < n; ++a)
                for (int b2 = 0; b2 < n; ++b2) {
                    G[a * n + b2] += Y[a] * Y[b2];
                    C[a * n + b2] += Y[a] * Yr[b2];
                }
            ++p;
        }
        double Gt[81] = {};
        for (int e = 0; e < n * n; ++e) Gt[e] = G[e];
        gsolve_c(n, n, Gt, C);               // C <- Dt
        double Ad[81] = {};
        for (int a = 0; a < n; ++a)
            for (int b2 = 0; b2 < n; ++b2)
                Ad[a * n + b2] = C[b2 * n + a];   // A = Dt^T
        double At[81] = {}, I[81] = {};
        for (int e = 0; e < n * n; ++e) At[e] = Ad[e];
        for (int a = 0; a < n; ++a) I[a * n + a] = 1.0;
        gsolve_c(n, n, At, I);               // I <- A^{-1}
        for (int e = 0; e < n * n; ++e) {
            g.A[CUMH[l] + e]    = (float)Ad[e];
            g.Ainv[CUMH[l] + e] = (float)I[e];
        }
    }

    // --- (l, i, k) enumeration: linear block index == thread index.
    {
        int t = 0;
        for (int l = 0; l < 5; ++l) {
            int n = 2 * l + 1;
            for (int i = 0; i < n; ++i)
                for (int k = 0; k < n; ++k) {
                    g.el[t] = (unsigned char)l;
                    g.ei[t] = (unsigned char)i;
                    g.ek[t] = (unsigned char)k;
                    ++t;
                }
        }
        for (int l = 0; l < 5; ++l) g.cum[l] = CUMH[l];
        for (int l = 5; l < 8; ++l) g.cum[l] = 0;
    }

    // --- Hot quad table: quads (4-column groups) intersecting each block row.
    {
        int off = 0, row = 0, w = 0;
        for (int l = 0; l < 5; ++l) {
            int n = 2 * l + 1;
            for (int c = 0; c < CNT[l]; ++c) {
                for (int i = 0; i < n; ++i) {
                    int qlo = off / 4;
                    int qhi = (off + n - 1) / 4;
                    for (int q = qlo; q <= qhi && w < NHOT_PAD; ++q) {
                        unsigned int packed = 0;
                        for (int j = 0; j < 4; ++j) {
                            int col = q * 4 + j;
                            unsigned int src = 0;
                            if (col >= off && col < off + n)
                                src = (unsigned int)(CUMH[l] + i * n + (col - off));
                            else
                                src = NBLK;   // sD[165] == 0
                            packed |= src << (8 * j);
                        }
                        g.hdst[w] = (short)(row * (DIMSZ / 4) + q);
                        g.hsrc[w] = packed;
                        ++w;
                    }
                    ++row;
                }
                off += n;
            }
        }
        for (; w < NHOT_PAD; ++w) { g.hdst[w] = g.hdst[0]; g.hsrc[w] = g.hsrc[0]; }
    }
    return g;
}

// Static (constant) initialization — baked into the cubin. No upload node,
// no host memory touched at graph replay. Global-space, L1-cached access.
__device__ const GTab gT = make_gtab();

// ---------------------------------------------------------------------------
// Fused kernel, one CTA per batch element — compute FIRST, then zero pass,
// then hot pass (phase order is load-bearing: front-loading the store burst
// regressed via cross-CTA L1tex queue contention, R6).
// ---------------------------------------------------------------------------
__global__ __launch_bounds__(256) void wigner_full(
    const float* __restrict__ alpha,
    const float* __restrict__ beta,
    const float* __restrict__ gamma,
    float4* __restrict__ out)
{
    __shared__ float s_tr[6][5];
    __shared__ float sM[NBLK];
    __shared__ float sD[NBLK + 3];

    const int b   = blockIdx.x;
    const int tid = threadIdx.x;

    // ---- Stage A: sincos(m*angle), m=0..4, three angles.
    if (tid < 15) {
        int which = tid / 5;
        int m     = tid - which * 5;
        float ang = (which == 0) ? alpha[b] : (which == 1) ? beta[b] : gamma[b];
        float s, c;
        sincosf((float)m * ang, &s, &c);
        s_tr[2 * which][m]     = c;
        s_tr[2 * which + 1][m] = s;
    }
    __syncthreads();

    // ---- Stage B: M = (A * Zbeta) * Ainv ; linear block index == tid.
    if (tid < NBLK) {
        const int l = gT.el[tid], i = gT.ei[tid], k = gT.ek[tid];
        const int n = 2 * l + 1;
        const int ab = __ldg(&gT.cum[l]);
        const int arow = ab + i * n;
        float acc = 0.f;
        for (int j = 0; j < n; ++j) {
            int mj = j - l;
            int am = mj < 0 ? -mj : mj;
            float cb = s_tr[2][am];
            float sb = (mj >= 0) ? s_tr[3][am] : -s_tr[3][am];
            float az = __ldg(&gT.A[arow + j]) * cb
                     + __ldg(&gT.A[arow + (n - 1 - j)]) * sb;
            acc += az * __ldg(&gT.Ainv[ab + j * n + k]);
        }
        sM[tid] = acc;
    } else if (tid < NBLK + 3) {
        sD[tid] = 0.f;          // pad slot: source index 165 reads zero
    }
    __syncthreads();

    // ---- Stage C: D = Zalpha * M * Zgamma
    if (tid < NBLK) {
        const int l = gT.el[tid], i = gT.ei[tid], k = gT.ek[tid];
        const int n = 2 * l + 1;
        const int ab = __ldg(&gT.cum[l]);
        const int ri = n - 1 - i, rk = n - 1 - k;
        const int mi = i - l, mk = k - l;
        const int ami = mi < 0 ? -mi : mi;
        const int amk = mk < 0 ? -mk : mk;
        float cai = s_tr[0][ami];
        float sai = (mi >= 0) ? s_tr[1][ami] : -s_tr[1][ami];
        float cgk = s_tr[4][amk];
        float sgk = (mk >= 0) ? s_tr[5][amk] : -s_tr[5][amk];
        float t0 = cai * sM[ab + i * n + k]  - sai * sM[ab + ri * n + k];
        float t1 = cai * sM[ab + i * n + rk] - sai * sM[ab + ri * n + rk];
        sD[tid] = t0 * cgk + t1 * sgk;
    }

    // ---- Zero pass: 11236 coalesced float4 zero stores (streaming hint).
    float4* ob = out + (size_t)b * QPB;
    const float4 z = make_float4(0.f, 0.f, 0.f, 0.f);
    #pragma unroll
    for (int u = 0; u < 43; ++u)        // 43*256 = 11008
        __stcs(&ob[u * 256 + tid], z);
    if (tid < QPB - 43 * 256)           // remainder 228
        __stcs(&ob[43 * 256 + tid], z);

    // CTA barrier: orders zero-pass WAW before hot overwrite, publishes sD.
    __syncthreads();

    // ---- Hot pass: exactly NHOT=432 quads (t in {tid, tid+256} < 432).
    #pragma unroll
    for (int u = 0; u < 2; ++u) {
        int t = u * 256 + tid;
        if (t < NHOT) {
            int          d = __ldg(&gT.hdst[t]);
            unsigned int s = __ldg(&gT.hsrc[t]);
            float4 v = make_float4(sD[s & 255],
                                   sD[(s >> 8) & 255],
                                   sD[(s >> 16) & 255],
                                   sD[s >> 24]);
            __stcs(&ob[d], v);
        }
    }
}

extern "C" void kernel_launch(void* const* d_in, const int* in_sizes, int n_in,
                              void* d_out, int out_size)
{
    const float* alpha = (const float*)d_in[0];
    const float* beta  = (const float*)d_in[1];
    const float* gamma = (const float*)d_in[2];
    int B = in_sizes[0];

    // Single graph node: all tables are baked into the module image.
    wigner_full<<<B, 256>>>(alpha, beta, gamma, (float4*)d_out);
}

// round 15
// speedup vs baseline: 1.3402x; 1.3402x over previous
#include <cuda_runtime.h>

// Problem geometry: IRREPS_L = [0]*32 + [1]*16 + [2]*8 + [3]*8 + [4]*4
// DIM = 32*1 + 16*3 + 8*5 + 8*7 + 4*9 = 212
#define NBLK 165            // sum of (2l+1)^2 over unique l
#define DIMSZ 212
#define QPB 11236           // float4 quads per batch matrix (212*212/4)
#define NHOT 432            // quads intersecting diagonal blocks
#define NHOT_PAD 512

struct GTab {
    float A[NBLK];
    float Ainv[NBLK];
    unsigned char el[NBLK + 3];
    unsigned char ei[NBLK + 3];
    unsigned char ek[NBLK + 3];
    unsigned char pad_[3];
    int cum[8];                    // {0,1,10,35,84,...}
    short        hdst[NHOT_PAD];   // quad index within 11236
    unsigned int hsrc[NHOT_PAD];   // 4 packed byte-indices into sD (165 => 0)
};

// ===========================================================================
// COMPILE-TIME construction of all tables (validated: rel_err 8.2e-8 in R14).
// ===========================================================================

constexpr double CPI = 3.14159265358979323846;

constexpr double cfabs(double x) { return x < 0 ? -x : x; }

constexpr double csqrt(double x) {
    if (x <= 0.0) return 0.0;
    double g = x > 1.0 ? x : 1.0;
    for (int i = 0; i < 100; ++i) g = 0.5 * (g + x / g);
    return g;
}

constexpr double dfact(int n) { double r = 1.0; for (int i = 2; i <= n; ++i) r *= (double)i; return r; }

constexpr double urand(unsigned long long& s) {
    s = s * 6364136223846793005ULL + 1442695040888963407ULL;
    return (double)(s >> 11) * (1.0 / 9007199254740992.0);   // [0,1)
}

constexpr void alegendre_c(int l, double x, double* res) {
    for (int m = 0; m <= l; ++m) {
        double pmm = 1.0;
        if (m > 0) {
            double somx2 = csqrt(1.0 - x * x > 0.0 ? 1.0 - x * x : 0.0);
            double fact = 1.0;
            for (int i = 0; i < m; ++i) { pmm = -pmm * fact * somx2; fact += 2.0; }
        }
        if (l == m) { res[m] = pmm; continue; }
        double pmmp1 = x * (2 * m + 1) * pmm;
        if (l == m + 1) { res[m] = pmmp1; continue; }
        double p0 = pmm, p1 = pmmp1, pll = 0.0;
        for (int ll = m + 2; ll <= l; ++ll) {
            pll = ((2 * ll - 1) * x * p1 - (ll + m - 1) * p0) / (ll - m);
            p0 = p1; p1 = pll;
        }
        res[m] = pll;
    }
}

// Real SH without trig: cos(m phi), sin(m phi) via Chebyshev recurrence.
constexpr void rsh_c(int l, double x, double y, double z,
                     const double* Nf, double sq2, double* out) {
    double P[5] = {};
    alegendre_c(l, z, P);
    double rho = csqrt(x * x + y * y);
    double c1 = 1.0, s1 = 0.0;
    if (rho > 1e-300) { c1 = x / rho; s1 = y / rho; }
    double cm[5] = {1.0, 0.0, 0.0, 0.0, 0.0};
    double sm[5] = {0.0, 0.0, 0.0, 0.0, 0.0};
    if (l >= 1) { cm[1] = c1; sm[1] = s1; }
    for (int m = 2; m <= l; ++m) {
        cm[m] = 2.0 * c1 * cm[m - 1] - cm[m - 2];
        sm[m] = 2.0 * c1 * sm[m - 1] - sm[m - 2];
    }
    for (int m = -l; m <= l; ++m) {
        int am = m < 0 ? -m : m;
        double v = 0.0;
        if (m == 0)      v = Nf[0] * P[0];
        else if (m > 0)  v = sq2 * Nf[am] * P[am] * cm[am];
        else             v = sq2 * Nf[am] * P[am] * sm[am];
        out[m + l] = v;
    }
}

// Solve A X = B in place (B <- X), partial pivoting.
constexpr void gsolve_c(int n, int m, double* A, double* B) {
    for (int col = 0; col < n; ++col) {
        int piv = col;
        for (int r2 = col + 1; r2 < n; ++r2)
            if (cfabs(A[r2 * n + col]) > cfabs(A[piv * n + col])) piv = r2;
        if (piv != col) {
            for (int c2 = 0; c2 < n; ++c2) { double t = A[col * n + c2]; A[col * n + c2] = A[piv * n + c2]; A[piv * n + c2] = t; }
            for (int c2 = 0; c2 < m; ++c2) { double t = B[col * m + c2]; B[col * m + c2] = B[piv * m + c2]; B[piv * m + c2] = t; }
        }
        double d = A[col * n + col];
        for (int c2 = col; c2 < n; ++c2) A[col * n + c2] /= d;
        for (int c2 = 0; c2 < m; ++c2) B[col * m + c2] /= d;
        for (int r2 = 0; r2 < n; ++r2) {
            if (r2 == col) continue;
            double f = A[r2 * n + col];
            if (f == 0.0) continue;
            for (int c2 = col; c2 < n; ++c2) A[r2 * n + c2] -= f * A[col * n + c2];
            for (int c2 = 0; c2 < m; ++c2) B[r2 * m + c2] -= f * B[col * m + c2];
        }
    }
}

constexpr GTab make_gtab() {
    GTab g = {};
    const int CNT[5]  = {32, 16, 8, 8, 4};
    const int CUMH[5] = {0, 1, 10, 35, 84};
    const double sq2 = csqrt(2.0);
    const int NP = 80;

    // --- Wigner matrices A (of Rx) and Ainv per l, via normal equations.
    for (int l = 0; l < 5; ++l) {
        int n = 2 * l + 1;
        double Nf[5] = {};
        for (int m = 0; m <= l; ++m)
            Nf[m] = csqrt((2 * l + 1) / (4.0 * CPI) * dfact(l - m) / dfact(l + m));

        double G[81] = {}, C[81] = {};
        unsigned long long seed = 0x9E3779B97F4A7C15ULL + (unsigned long long)l;
        int p = 0;
        int guard = 0;
        while (p < NP && guard < 4 * NP) {
            ++guard;
            double x = 2.0 * urand(seed) - 1.0;
            double y = 2.0 * urand(seed) - 1.0;
            double z = 2.0 * urand(seed) - 1.0;
            double r2 = x * x + y * y + z * z;
            if (r2 < 0.05 || r2 > 1.0) continue;
            double r = csqrt(r2);
            x /= r; y /= r; z /= r;
            double Y[9] = {}, Yr[9] = {};
            rsh_c(l, x, y, z, Nf, sq2, Y);
            rsh_c(l, x, z, -y, Nf, sq2, Yr);   // R = Rx: (x,y,z) -> (x, z, -y)
            for (int a = 0; a < n; ++a)
                for (int b2 = 0; b2 < n; ++b2) {
                    G[a * n + b2] += Y[a] * Y[b2];
                    C[a * n + b2] += Y[a] * Yr[b2];
                }
            ++p;
        }
        double Gt[81] = {};
        for (int e = 0; e < n * n; ++e) Gt[e] = G[e];
        gsolve_c(n, n, Gt, C);               // C <- Dt
        double Ad[81] = {};
        for (int a = 0; a < n; ++a)
            for (int b2 = 0; b2 < n; ++b2)
                Ad[a * n + b2] = C[b2 * n + a];   // A = Dt^T
        double At[81] = {}, I[81] = {};
        for (int e = 0; e < n * n; ++e) At[e] = Ad[e];
        for (int a = 0; a < n; ++a) I[a * n + a] = 1.0;
        gsolve_c(n, n, At, I);               // I <- A^{-1}
        for (int e = 0; e < n * n; ++e) {
            g.A[CUMH[l] + e]    = (float)Ad[e];
            g.Ainv[CUMH[l] + e] = (float)I[e];
        }
    }

    // --- (l, i, k) enumeration: linear block index == thread index.
    {
        int t = 0;
        for (int l = 0; l < 5; ++l) {
            int n = 2 * l + 1;
            for (int i = 0; i < n; ++i)
                for (int k = 0; k < n; ++k) {
                    g.el[t] = (unsigned char)l;
                    g.ei[t] = (unsigned char)i;
                    g.ek[t] = (unsigned char)k;
                    ++t;
                }
        }
        for (int l = 0; l < 5; ++l) g.cum[l] = CUMH[l];
        for (int l = 5; l < 8; ++l) g.cum[l] = 0;
    }

    // --- Hot quad table: quads (4-column groups) intersecting each block row.
    {
        int off = 0, row = 0, w = 0;
        for (int l = 0; l < 5; ++l) {
            int n = 2 * l + 1;
            for (int c = 0; c < CNT[l]; ++c) {
                for (int i = 0; i < n; ++i) {
                    int qlo = off / 4;
                    int qhi = (off + n - 1) / 4;
                    for (int q = qlo; q <= qhi && w < NHOT_PAD; ++q) {
                        unsigned int packed = 0;
                        for (int j = 0; j < 4; ++j) {
                            int col = q * 4 + j;
                            unsigned int src = 0;
                            if (col >= off && col < off + n)
                                src = (unsigned int)(CUMH[l] + i * n + (col - off));
                            else
                                src = NBLK;   // sD[165] == 0
                            packed |= src << (8 * j);
                        }
                        g.hdst[w] = (short)(row * (DIMSZ / 4) + q);
                        g.hsrc[w] = packed;
                        ++w;
                    }
                    ++row;
                }
                off += n;
            }
        }
        for (; w < NHOT_PAD; ++w) { g.hdst[w] = g.hdst[0]; g.hsrc[w] = g.hsrc[0]; }
    }
    return g;
}

// Statically initialized but NON-const: a mutable __device__ global cannot be
// promoted to the constant bank, so all table accesses stay on the L1-cached
// LDG path (R14 lesson: `__device__ const` + known initializer let the
// compiler retarget divergently-indexed loads to LDC -> replay serialization,
// 84us). Still baked into the module image: graph remains a single node.
__device__ GTab gT = make_gtab();

// ---------------------------------------------------------------------------
// Fused kernel, one CTA per batch element — compute FIRST, then zero pass,
// then hot pass (phase order is load-bearing, R6).
// ---------------------------------------------------------------------------
__global__ __launch_bounds__(256) void wigner_full(
    const float* __restrict__ alpha,
    const float* __restrict__ beta,
    const float* __restrict__ gamma,
    float4* __restrict__ out)
{
    __shared__ float s_tr[6][5];
    __shared__ float sM[NBLK];
    __shared__ float sD[NBLK + 3];

    const int b   = blockIdx.x;
    const int tid = threadIdx.x;

    // ---- Stage A: sincos(m*angle), m=0..4, three angles.
    if (tid < 15) {
        int which = tid / 5;
        int m     = tid - which * 5;
        float ang = (which == 0) ? alpha[b] : (which == 1) ? beta[b] : gamma[b];
        float s, c;
        sincosf((float)m * ang, &s, &c);
        s_tr[2 * which][m]     = c;
        s_tr[2 * which + 1][m] = s;
    }
    __syncthreads();

    // ---- Stage B: M = (A * Zbeta) * Ainv ; linear block index == tid.
    if (tid < NBLK) {
        const int l = gT.el[tid], i = gT.ei[tid], k = gT.ek[tid];
        const int n = 2 * l + 1;
        const int ab = __ldg((const int*)&gT.cum[l]);
        const int arow = ab + i * n;
        float acc = 0.f;
        for (int j = 0; j < n; ++j) {
            int mj = j - l;
            int am = mj < 0 ? -mj : mj;
            float cb = s_tr[2][am];
            float sb = (mj >= 0) ? s_tr[3][am] : -s_tr[3][am];
            float az = __ldg((const float*)&gT.A[arow + j]) * cb
                     + __ldg((const float*)&gT.A[arow + (n - 1 - j)]) * sb;
            acc += az * __ldg((const float*)&gT.Ainv[ab + j * n + k]);
        }
        sM[tid] = acc;
    } else if (tid < NBLK + 3) {
        sD[tid] = 0.f;          // pad slot: source index 165 reads zero
    }
    __syncthreads();

    // ---- Stage C: D = Zalpha * M * Zgamma
    if (tid < NBLK) {
        const int l = gT.el[tid], i = gT.ei[tid], k = gT.ek[tid];
        const int n = 2 * l + 1;
        const int ab = __ldg((const int*)&gT.cum[l]);
        const int ri = n - 1 - i, rk = n - 1 - k;
        const int mi = i - l, mk = k - l;
        const int ami = mi < 0 ? -mi : mi;
        const int amk = mk < 0 ? -mk : mk;
        float cai = s_tr[0][ami];
        float sai = (mi >= 0) ? s_tr[1][ami] : -s_tr[1][ami];
        float cgk = s_tr[4][amk];
        float sgk = (mk >= 0) ? s_tr[5][amk] : -s_tr[5][amk];
        float t0 = cai * sM[ab + i * n + k]  - sai * sM[ab + ri * n + k];
        float t1 = cai * sM[ab + i * n + rk] - sai * sM[ab + ri * n + rk];
        sD[tid] = t0 * cgk + t1 * sgk;
    }

    // ---- Zero pass: 11236 coalesced float4 zero stores (streaming hint).
    float4* ob = out + (size_t)b * QPB;
    const float4 z = make_float4(0.f, 0.f, 0.f, 0.f);
    #pragma unroll
    for (int u = 0; u < 43; ++u)        // 43*256 = 11008
        __stcs(&ob[u * 256 + tid], z);
    if (tid < QPB - 43 * 256)           // remainder 228
        __stcs(&ob[43 * 256 + tid], z);

    // CTA barrier: orders zero-pass WAW before hot overwrite, publishes sD.
    __syncthreads();

    // ---- Hot pass: exactly NHOT=432 quads (t in {tid, tid+256} < 432).
    #pragma unroll
    for (int u = 0; u < 2; ++u) {
        int t = u * 256 + tid;
        if (t < NHOT) {
            int          d = __ldg((const short*)&gT.hdst[t]);
            unsigned int s = __ldg((const unsigned int*)&gT.hsrc[t]);
            float4 v = make_float4(sD[s & 255],
                                   sD[(s >> 8) & 255],
                                   sD[(s >> 16) & 255],
                                   sD[s >> 24]);
            __stcs(&ob[d], v);
        }
    }
}

extern "C" void kernel_launch(void* const* d_in, const int* in_sizes, int n_in,
                              void* d_out, int out_size)
{
    const float* alpha = (const float*)d_in[0];
    const float* beta  = (const float*)d_in[1];
    const float* gamma = (const float*)d_in[2];
    int B = in_sizes[0];

    // Single graph node: all tables are baked into the module image.
    wigner_full<<<B, 256>>>(alpha, beta, gamma, (float4*)d_out);
}